// round 12
// baseline (speedup 1.0000x reference)
#include <cuda_runtime.h>
#include <cuda_bf16.h>
#include <cstdint>

// DynamicMaskHead: 128 instances, MLP 10 -> 8 -> 8 -> 1 over 160x160 px (fp32).
// Persistent single-wave pipeline (592 CTAs = 4/SM). R12: feature tiles are
// fetched with cp.async.bulk (TMA/UBLKCP, async proxy) issued by one thread,
// completing on an mbarrier — zero per-thread fill instructions, no L1TEX
// fill wavefronts. 2-stage smem ring, one __syncthreads per tile to re-arm.

#define NINST 128
#define CIN   10
#define CMID  8
#define HW    25600
#define HW4   (HW / 4)
#define TPB   128
#define TILE4 128                       // float4 per tile (512 px)
#define TILES_PER_INST 50
#define NSTAGE 2
#define NCTA 592                        // 4 per SM, one wave

#define SMEM_TILE_F4 (CIN * TILE4)      // 1280 float4 per stage
#define STAGE_BYTES (SMEM_TILE_F4 * 16) // 20480
#define CH_BYTES (TILE4 * 16)           // 2048 per channel chunk
#define DYN_SMEM_BYTES (NSTAGE * STAGE_BYTES)   // 40960

__device__ __forceinline__ float2 ffma2(float2 a, float2 b, float2 c) {
    float2 d;
    asm("fma.rn.f32x2 %0, %1, %2, %3;"
        : "=l"(reinterpret_cast<unsigned long long&>(d))
        : "l"(reinterpret_cast<unsigned long long&>(a)),
          "l"(reinterpret_cast<unsigned long long&>(b)),
          "l"(reinterpret_cast<unsigned long long&>(c)));
    return d;
}

__device__ __forceinline__ float2 relu2(float2 a) {
    return make_float2(fmaxf(a.x, 0.0f), fmaxf(a.y, 0.0f));
}

__device__ __forceinline__ void mbar_init(uint32_t mbar, uint32_t cnt) {
    asm volatile("mbarrier.init.shared.b64 [%0], %1;" :: "r"(mbar), "r"(cnt) : "memory");
}
__device__ __forceinline__ void mbar_expect_tx(uint32_t mbar, uint32_t bytes) {
    asm volatile("mbarrier.arrive.expect_tx.shared.b64 _, [%0], %1;"
                 :: "r"(mbar), "r"(bytes) : "memory");
}
__device__ __forceinline__ void mbar_wait(uint32_t mbar, uint32_t parity) {
    uint32_t done;
    asm volatile(
        "{\n\t.reg .pred p;\n\t"
        "mbarrier.try_wait.parity.acquire.cta.shared::cta.b64 p, [%1], %2;\n\t"
        "selp.b32 %0, 1, 0, p;\n\t}"
        : "=r"(done) : "r"(mbar), "r"(parity) : "memory");
    if (!done) {
        asm volatile(
            "{\n\t.reg .pred P1;\n\t"
            "WL_%=:\n\t"
            "mbarrier.try_wait.parity.acquire.cta.shared::cta.b64 P1, [%0], %1, 0x989680;\n\t"
            "@P1 bra.uni WD_%=;\n\t"
            "bra.uni WL_%=;\n\t"
            "WD_%=:\n\t}"
            :: "r"(mbar), "r"(parity) : "memory");
    }
}
__device__ __forceinline__ void bulk_cp(uint32_t dst, const void* src,
                                        uint32_t bytes, uint32_t mbar) {
    asm volatile(
        "cp.async.bulk.shared::cluster.global.mbarrier::complete_tx::bytes "
        "[%0], [%1], %2, [%3];"
        :: "r"(dst), "l"(src), "r"(bytes), "r"(mbar) : "memory");
}

__global__ void __launch_bounds__(TPB, 4)
mask_head_kernel(const float* __restrict__ feat,
                 const float* __restrict__ params,
                 float* __restrict__ out) {
    extern __shared__ float4 fbuf[];    // [NSTAGE][CIN][TILE4]

    __shared__ __align__(8) uint64_t mbar_s[NSTAGE];
    // Double-buffered weight sets, duplicated float2 halves (LDS.64 -> FFMA2).
    __shared__ float2 w0s[2][CMID * CIN];
    __shared__ float2 w1s[2][CMID * CMID];
    __shared__ float2 w2s[2][CMID];
    __shared__ float2 b0s[2][CMID];
    __shared__ float2 b1s[2][CMID];
    __shared__ float2 b2s[2];

    const int tid = threadIdx.x;
    const int b   = blockIdx.x;

    // 6400 tiles over 592 CTAs: first 480 get 11, remaining 112 get 10.
    int first, count;
    if (b < 480) { first = b * 11;                count = 11; }
    else         { first = 5280 + (b - 480) * 10; count = 10; }

    const int inst0 = first / TILES_PER_INST;
    const int inst1 = (first + count - 1) / TILES_PER_INST;

    const char* fbytes = reinterpret_cast<const char*>(feat);
    float4* out4 = reinterpret_cast<float4*>(out);
    const uint32_t sbase = (uint32_t)__cvta_generic_to_shared(fbuf);
    const uint32_t mbase = (uint32_t)__cvta_generic_to_shared(mbar_s);

    if (tid == 0) {
        mbar_init(mbase,     1);
        mbar_init(mbase + 8, 1);
    }
    __syncthreads();   // mbarrier init visible to all

    // One elected thread fetches a whole tile: 10 x 2 KB bulk copies.
    auto issue_tma = [&](int item, int stage) {
        if (tid == 0) {
            const int inst = item / TILES_PER_INST;
            const int tile = item % TILES_PER_INST;
            const uint32_t mb = mbase + stage * 8;
            mbar_expect_tx(mb, STAGE_BYTES);
            const char* g = fbytes + (size_t)inst * CIN * HW * 4 + tile * CH_BYTES;
            uint32_t s = sbase + stage * STAGE_BYTES;
#pragma unroll
            for (int k = 0; k < CIN; k++) {
                bulk_cp(s, g, CH_BYTES, mb);
                g += HW * 4;          // next channel plane
                s += CH_BYTES;
            }
        }
    };

    issue_tma(first, 0);
    if (count > 1) issue_tma(first + 1, 1);
    int issued = (count > 1) ? 2 : 1;

    // Weight preload overlaps the in-flight TMA.
    for (int i = tid; i < 169; i += TPB) {
        float va = params[inst0 * 169 + i];
        float vb = params[inst1 * 169 + i];
        float2 a2  = make_float2(va, va);
        float2 b2v = make_float2(vb, vb);
        if      (i < 80)  { w0s[0][i]       = a2; w0s[1][i]       = b2v; }
        else if (i < 144) { w1s[0][i - 80]  = a2; w1s[1][i - 80]  = b2v; }
        else if (i < 152) { w2s[0][i - 144] = a2; w2s[1][i - 144] = b2v; }
        else if (i < 160) { b0s[0][i - 152] = a2; b0s[1][i - 152] = b2v; }
        else if (i < 168) { b1s[0][i - 160] = a2; b1s[1][i - 160] = b2v; }
        else              { b2s[0]          = a2; b2s[1]          = b2v; }
    }
    __syncthreads();   // weights visible

    int phase[NSTAGE] = {0, 0};

    for (int i = 0; i < count; i++) {
        const int item = first + i;
        const int inst = item / TILES_PER_INST;
        const int tile = item % TILES_PER_INST;
        const int wsel = (inst != inst0) ? 1 : 0;
        const int stage = i & 1;

        mbar_wait(mbase + stage * 8, phase[stage]);
        phase[stage] ^= 1;

        const float4* sb = fbuf + stage * SMEM_TILE_F4 + tid;
        const float2* w0p = w0s[wsel];
        const float2* w1p = w1s[wsel];
        const float2* w2p = w2s[wsel];
        const float2* b0p = b0s[wsel];
        const float2* b1p = b1s[wsel];

        // ---- Layer 0 (10 -> 8, ReLU), 4 px = 2 f32x2 lanes ----
        float2 h0[CMID][2];
#pragma unroll
        for (int o = 0; o < CMID; o++) {
            float2 bb = b0p[o];
            h0[o][0] = bb; h0[o][1] = bb;
        }
#pragma unroll
        for (int k = 0; k < CIN; k++) {
            float4 v = sb[k * TILE4];
            float2 x0 = make_float2(v.x, v.y);
            float2 x1 = make_float2(v.z, v.w);
#pragma unroll
            for (int o = 0; o < CMID; o++) {
                float2 w = w0p[o * CIN + k];
                h0[o][0] = ffma2(w, x0, h0[o][0]);
                h0[o][1] = ffma2(w, x1, h0[o][1]);
            }
        }
#pragma unroll
        for (int o = 0; o < CMID; o++) {
            h0[o][0] = relu2(h0[o][0]);
            h0[o][1] = relu2(h0[o][1]);
        }

        // ---- Layers 1+2 fused ----
        float2 acc0, acc1;
        {
            float2 bb = b2s[wsel];
            acc0 = bb; acc1 = bb;
        }
#pragma unroll
        for (int o = 0; o < CMID; o++) {
            float2 bb = b1p[o];
            float2 t0 = bb, t1 = bb;
#pragma unroll
            for (int k = 0; k < CMID; k++) {
                float2 w = w1p[o * CMID + k];
                t0 = ffma2(w, h0[k][0], t0);
                t1 = ffma2(w, h0[k][1], t1);
            }
            float2 w2 = w2p[o];
            acc0 = ffma2(w2, relu2(t0), acc0);
            acc1 = ffma2(w2, relu2(t1), acc1);
        }

        out4[inst * HW4 + tile * TILE4 + tid] =
            make_float4(acc0.x, acc0.y, acc1.x, acc1.y);

        // All readers done with this stage before TMA overwrites it.
        __syncthreads();
        if (issued < count) { issue_tma(first + issued, issued & 1); issued++; }
    }
}

extern "C" void kernel_launch(void* const* d_in, const int* in_sizes, int n_in,
                              void* d_out, int out_size) {
    const float* feat   = (const float*)d_in[0];
    const float* params = (const float*)d_in[1];
    float* out          = (float*)d_out;

    cudaFuncSetAttribute(mask_head_kernel,
                         cudaFuncAttributeMaxDynamicSharedMemorySize,
                         DYN_SMEM_BYTES);

    mask_head_kernel<<<NCTA, TPB, DYN_SMEM_BYTES>>>(feat, params, out);
}

// round 14
// speedup vs baseline: 1.2433x; 1.2433x over previous
#include <cuda_runtime.h>
#include <cuda_bf16.h>
#include <cstdint>

// DynamicMaskHead: 128 instances, MLP 10 -> 8 -> 8 -> 1 over 160x160 px (fp32).
// Persistent barrier-free cp.async pipeline (R8 structure, proven best),
// rescheduled to 5 CTAs/SM (740 CTAs, single wave) = 5 warps/SMSP to fill
// the dependency-stall holes that bound the 4-CTA version.

#define NINST 128
#define CIN   10
#define CMID  8
#define HW    25600
#define HW4   (HW / 4)
#define TPB   128
#define TILE4 128                       // float4 per tile (512 px)
#define TILES_PER_INST 50
#define NSTAGE 2
#define NCTA 740                        // 5 per SM, one wave

#define SMEM_TILE_F4 (CIN * TILE4)      // 1280 float4 per stage (20 KB)
#define DYN_SMEM_BYTES (NSTAGE * SMEM_TILE_F4 * 16)   // 40960

__device__ __forceinline__ float2 ffma2(float2 a, float2 b, float2 c) {
    float2 d;
    asm("fma.rn.f32x2 %0, %1, %2, %3;"
        : "=l"(reinterpret_cast<unsigned long long&>(d))
        : "l"(reinterpret_cast<unsigned long long&>(a)),
          "l"(reinterpret_cast<unsigned long long&>(b)),
          "l"(reinterpret_cast<unsigned long long&>(c)));
    return d;
}

__device__ __forceinline__ float2 relu2(float2 a) {
    return make_float2(fmaxf(a.x, 0.0f), fmaxf(a.y, 0.0f));
}

__device__ __forceinline__ void cp16(uint32_t dst_smem, const float4* src) {
    asm volatile("cp.async.cg.shared.global [%0], [%1], 16;"
                 :: "r"(dst_smem), "l"(src));
}

__global__ void __launch_bounds__(TPB, 5)
mask_head_kernel(const float* __restrict__ feat,
                 const float* __restrict__ params,
                 float* __restrict__ out) {
    extern __shared__ float4 fbuf[];    // [NSTAGE][CIN][TILE4]

    // Double-buffered weight sets (a CTA's run spans <= 2 instances),
    // duplicated float2 halves: LDS.64 broadcast feeds fma.rn.f32x2 directly.
    __shared__ float2 w0s[2][CMID * CIN];
    __shared__ float2 w1s[2][CMID * CMID];
    __shared__ float2 w2s[2][CMID];
    __shared__ float2 b0s[2][CMID];
    __shared__ float2 b1s[2][CMID];
    __shared__ float2 b2s[2];

    const int tid = threadIdx.x;
    const int b   = blockIdx.x;

    // 6400 tiles over 740 CTAs: first 480 get 9, remaining 260 get 8.
    int first, count;
    if (b < 480) { first = b * 9;                count = 9; }
    else         { first = 4320 + (b - 480) * 8; count = 8; }

    const int inst0 = first / TILES_PER_INST;
    const int inst1 = (first + count - 1) / TILES_PER_INST;  // inst0 or inst0+1

    const float4* fin4 = reinterpret_cast<const float4*>(feat);
    float4* out4 = reinterpret_cast<float4*>(out);
    const uint32_t sbase = (uint32_t)__cvta_generic_to_shared(fbuf);

    // 10 cp.asyncs per item; thread tid owns float4 slot tid of each channel.
    auto issue_item = [&](int item, int stage) {
        const int inst = item / TILES_PER_INST;
        const int tile = item % TILES_PER_INST;
        const float4* g = fin4 + inst * CIN * HW4 + tile * TILE4 + tid;
        uint32_t s = sbase + (stage * SMEM_TILE_F4 + tid) * 16;
#pragma unroll
        for (int k = 0; k < CIN; k++) {
            cp16(s, g);
            g += HW4;
            s += TILE4 * 16;
        }
        asm volatile("cp.async.commit_group;");
    };

    // Prime the pipeline so DRAM streams immediately.
    int issued = 0;
    issue_item(first, 0); issued = 1;
    if (count > 1) { issue_item(first + 1, 1); issued = 2; }

    // Preload both weight sets (overlapped with the primed cp.asyncs).
    for (int i = tid; i < 169; i += TPB) {
        float va = params[inst0 * 169 + i];
        float vb = params[inst1 * 169 + i];
        float2 a2  = make_float2(va, va);
        float2 b2v = make_float2(vb, vb);
        if      (i < 80)  { w0s[0][i]       = a2; w0s[1][i]       = b2v; }
        else if (i < 144) { w1s[0][i - 80]  = a2; w1s[1][i - 80]  = b2v; }
        else if (i < 152) { w2s[0][i - 144] = a2; w2s[1][i - 144] = b2v; }
        else if (i < 160) { b0s[0][i - 152] = a2; b0s[1][i - 152] = b2v; }
        else if (i < 168) { b1s[0][i - 160] = a2; b1s[1][i - 160] = b2v; }
        else              { b2s[0]          = a2; b2s[1]          = b2v; }
    }
    __syncthreads();   // only block barrier in the kernel

    for (int i = 0; i < count; i++) {
        const int item = first + i;
        const int inst = item / TILES_PER_INST;
        const int tile = item % TILES_PER_INST;
        const int wsel = (inst != inst0) ? 1 : 0;
        const int stage = i & 1;

        // Wait for this item's group (groups complete in order; per-thread).
        if (issued > i + 1) asm volatile("cp.async.wait_group 1;");
        else                asm volatile("cp.async.wait_group 0;");

        const float4* sb = fbuf + stage * SMEM_TILE_F4 + tid;
        const float2* w0p = w0s[wsel];
        const float2* w1p = w1s[wsel];
        const float2* w2p = w2s[wsel];
        const float2* b0p = b0s[wsel];
        const float2* b1p = b1s[wsel];

        // ---- Layer 0 (10 -> 8, ReLU), 4 px = 2 f32x2 lanes ----
        float2 h0[CMID][2];
#pragma unroll
        for (int o = 0; o < CMID; o++) {
            float2 bb = b0p[o];
            h0[o][0] = bb; h0[o][1] = bb;
        }
#pragma unroll
        for (int k = 0; k < CIN; k++) {
            float4 v = sb[k * TILE4];
            float2 x0 = make_float2(v.x, v.y);
            float2 x1 = make_float2(v.z, v.w);
#pragma unroll
            for (int o = 0; o < CMID; o++) {
                float2 w = w0p[o * CIN + k];
                h0[o][0] = ffma2(w, x0, h0[o][0]);
                h0[o][1] = ffma2(w, x1, h0[o][1]);
            }
        }
#pragma unroll
        for (int o = 0; o < CMID; o++) {
            h0[o][0] = relu2(h0[o][0]);
            h0[o][1] = relu2(h0[o][1]);
        }

        // ---- Layers 1+2 fused ----
        float2 acc0, acc1;
        {
            float2 bb = b2s[wsel];
            acc0 = bb; acc1 = bb;
        }
#pragma unroll
        for (int o = 0; o < CMID; o++) {
            float2 bb = b1p[o];
            float2 t0 = bb, t1 = bb;
#pragma unroll
            for (int k = 0; k < CMID; k++) {
                float2 w = w1p[o * CMID + k];
                t0 = ffma2(w, h0[k][0], t0);
                t1 = ffma2(w, h0[k][1], t1);
            }
            float2 w2 = w2p[o];
            acc0 = ffma2(w2, relu2(t0), acc0);
            acc1 = ffma2(w2, relu2(t1), acc1);
        }

        out4[inst * HW4 + tile * TILE4 + tid] =
            make_float4(acc0.x, acc0.y, acc1.x, acc1.y);

        // Refill the freed stage (no barrier: this thread's slots only, and
        // its LDS reads were consumed by the FFMAs above).
        if (issued < count) { issue_item(first + issued, issued & 1); issued++; }
    }
}

extern "C" void kernel_launch(void* const* d_in, const int* in_sizes, int n_in,
                              void* d_out, int out_size) {
    const float* feat   = (const float*)d_in[0];
    const float* params = (const float*)d_in[1];
    float* out          = (float*)d_out;

    cudaFuncSetAttribute(mask_head_kernel,
                         cudaFuncAttributeMaxDynamicSharedMemorySize,
                         DYN_SMEM_BYTES);

    mask_head_kernel<<<NCTA, TPB, DYN_SMEM_BYTES>>>(feat, params, out);
}